// round 8
// baseline (speedup 1.0000x reference)
#include <cuda_runtime.h>

#define BATCH      1024
#define INPUT_DIM  1024
#define NB_K       32
#define KDIM       16
#define OUT_COLS   (INPUT_DIM + NB_K)   // 1056

__device__ float g_act[(size_t)NB_K * BATCH * KDIM];   // 2 MB

// ---- packed f32x2 helpers -------------------------------------------------
#define FMA_F32X2(d, a, b, c) \
    asm("fma.rn.f32x2 %0, %1, %2, %3;" : "=l"(d) : "l"(a), "l"(b), "l"(c))
#define PACK_F32X2(d, lo, hi) \
    asm("mov.b64 %0, {%1, %2};" : "=l"(d) : "f"(lo), "f"(hi))

// ---------------------------------------------------------------------------
// Kernel A: act[k][b][m] = sum_d x[b][d] * W[k][d][m]   (fused d-reduction)
// grid = (32 k, 16 b-tiles of 64) = 512 blocks, block = 256 = 8 warps.
// Warp w owns d-range [w*128, w*128+128); lane owns rows {b0+lane, b0+lane+32}.
// x: global->regs (L2-resident, never smem). W: warp-private smem staging.
// Per dd: 4 LDS.128 (W, broadcast) + 2 dup-packs + 16 FMA2.
// Cross-warp d-reduction through smem at the end (no g_part, no reduce kernel).
// ---------------------------------------------------------------------------
__global__ void __launch_bounds__(256, 2) mbd_gemm_kernel(
    const float* __restrict__ x, const float* __restrict__ W)
{
    const int k    = blockIdx.x;
    const int b0   = blockIdx.y * 64;
    const int tid  = threadIdx.x;
    const int lane = tid & 31;
    const int w    = tid >> 5;          // d-group

    __shared__ float sw[8][32][16];     // per-warp W tile: 16 KB
    __shared__ float red[8][64][16];    // cross-warp reduce buf: 32 KB

    unsigned long long accA[8], accB[8];
#pragma unroll
    for (int j = 0; j < 8; j++) { accA[j] = 0ull; accB[j] = 0ull; }

    const int rA = b0 + lane;
    const int rB = b0 + lane + 32;
    const float4* x4  = reinterpret_cast<const float4*>(x);
    const float4* Wk4 = reinterpret_cast<const float4*>(
        W + (size_t)k * INPUT_DIM * KDIM);
    float4* swf4 = reinterpret_cast<float4*>(&sw[w][0][0]);

    for (int c = 0; c < 4; c++) {
        const int d0 = w * 128 + c * 32;

        // stage W[k][d0..d0+32][0..16]: 128 float4, 4 per lane (warp-private)
#pragma unroll
        for (int i = 0; i < 4; i++)
            swf4[lane + i * 32] = Wk4[d0 * 4 + lane + i * 32];
        __syncwarp();

        // x chunks for both rows: 8 float4 each, straight to registers
        float4 xa[8], xb[8];
#pragma unroll
        for (int i = 0; i < 8; i++) {
            xa[i] = x4[(size_t)rA * (INPUT_DIM / 4) + (d0 >> 2) + i];
            xb[i] = x4[(size_t)rB * (INPUT_DIM / 4) + (d0 >> 2) + i];
        }

#pragma unroll
        for (int i = 0; i < 8; i++) {
            float va[4] = { xa[i].x, xa[i].y, xa[i].z, xa[i].w };
            float vb[4] = { xb[i].x, xb[i].y, xb[i].z, xb[i].w };
#pragma unroll
            for (int j4 = 0; j4 < 4; j4++) {
                const int dd = i * 4 + j4;
                unsigned long long da, db;
                PACK_F32X2(da, va[j4], va[j4]);
                PACK_F32X2(db, vb[j4], vb[j4]);
                const ulonglong2* wp =
                    reinterpret_cast<const ulonglong2*>(&sw[w][dd][0]);
                ulonglong2 w0 = wp[0], w1 = wp[1], w2 = wp[2], w3 = wp[3];
                FMA_F32X2(accA[0], w0.x, da, accA[0]);
                FMA_F32X2(accA[1], w0.y, da, accA[1]);
                FMA_F32X2(accA[2], w1.x, da, accA[2]);
                FMA_F32X2(accA[3], w1.y, da, accA[3]);
                FMA_F32X2(accA[4], w2.x, da, accA[4]);
                FMA_F32X2(accA[5], w2.y, da, accA[5]);
                FMA_F32X2(accA[6], w3.x, da, accA[6]);
                FMA_F32X2(accA[7], w3.y, da, accA[7]);
                FMA_F32X2(accB[0], w0.x, db, accB[0]);
                FMA_F32X2(accB[1], w0.y, db, accB[1]);
                FMA_F32X2(accB[2], w1.x, db, accB[2]);
                FMA_F32X2(accB[3], w1.y, db, accB[3]);
                FMA_F32X2(accB[4], w2.x, db, accB[4]);
                FMA_F32X2(accB[5], w2.y, db, accB[5]);
                FMA_F32X2(accB[6], w3.x, db, accB[6]);
                FMA_F32X2(accB[7], w3.y, db, accB[7]);
            }
        }
        __syncwarp();   // chunk consumed before restage
    }

    // ---- cross-warp reduction over the 8 d-groups ----
    __syncthreads();
    {
        // packed f32x2 pair (m, m+1) is bit-identical to two floats in order
        ulonglong2* ra = reinterpret_cast<ulonglong2*>(&red[w][lane][0]);
        ra[0] = make_ulonglong2(accA[0], accA[1]);
        ra[1] = make_ulonglong2(accA[2], accA[3]);
        ra[2] = make_ulonglong2(accA[4], accA[5]);
        ra[3] = make_ulonglong2(accA[6], accA[7]);
        ulonglong2* rb = reinterpret_cast<ulonglong2*>(&red[w][lane + 32][0]);
        rb[0] = make_ulonglong2(accB[0], accB[1]);
        rb[1] = make_ulonglong2(accB[2], accB[3]);
        rb[2] = make_ulonglong2(accB[4], accB[5]);
        rb[3] = make_ulonglong2(accB[6], accB[7]);
    }
    __syncthreads();
    {
        // 64 rows x 4 float4 = 256 outputs, one per thread
        const int row = tid >> 2;
        const int mg  = tid & 3;
        float4 s = *reinterpret_cast<const float4*>(&red[0][row][mg * 4]);
#pragma unroll
        for (int ww = 1; ww < 8; ww++) {
            float4 t = *reinterpret_cast<const float4*>(&red[ww][row][mg * 4]);
            s.x += t.x; s.y += t.y; s.z += t.z; s.w += t.w;
        }
        reinterpret_cast<float4*>(
            g_act + ((size_t)k * BATCH + b0 + row) * KDIM)[mg] = s;
    }
}

// ---------------------------------------------------------------------------
// Kernel B: feat[b][k] = sum_c exp(-sum_m |act[k][b][m] - act[k][c][m]|)
// Verified scalar version (abs folds into FADD src modifiers) + folded x-copy.
// grid = (32 k, 4 b-tiles), block = 256 (one b per thread).
// ---------------------------------------------------------------------------
__global__ void __launch_bounds__(256) mbd_pairwise_kernel(
    const float* __restrict__ x, float* __restrict__ out)
{
    const int k   = blockIdx.x;
    const int tid = threadIdx.x;
    const int b   = blockIdx.y * 256 + tid;

    __shared__ float4 sa[512 * 4];   // 512 rows x 16 floats = 32 KB

    // ---- folded copy: each of the 128 blocks copies 8 rows of x ----
    {
        const int id = blockIdx.x * 4 + blockIdx.y;       // 0..127
        const float4* x4 = reinterpret_cast<const float4*>(x);
        float4*       o4 = reinterpret_cast<float4*>(out);
#pragma unroll
        for (int i = 0; i < 8; i++) {
            int row = id * 8 + i;
            o4[(size_t)row * (OUT_COLS / 4) + tid] =
                x4[(size_t)row * (INPUT_DIM / 4) + tid];
        }
    }

    const float4* actk = reinterpret_cast<const float4*>(
        g_act + (size_t)k * BATCH * KDIM);

    float4 a0 = actk[b * 4 + 0];
    float4 a1 = actk[b * 4 + 1];
    float4 a2 = actk[b * 4 + 2];
    float4 a3 = actk[b * 4 + 3];

    float f = 0.f;

    for (int c0 = 0; c0 < BATCH; c0 += 512) {
        __syncthreads();
#pragma unroll
        for (int i = 0; i < 8; i++)
            sa[tid + i * 256] = actk[c0 * 4 + tid + i * 256];
        __syncthreads();

#pragma unroll 4
        for (int c = 0; c < 512; c++) {
            float4 v0 = sa[c * 4 + 0];
            float4 v1 = sa[c * 4 + 1];
            float4 v2 = sa[c * 4 + 2];
            float4 v3 = sa[c * 4 + 3];
            float s0 = fabsf(a0.x - v0.x) + fabsf(a0.y - v0.y)
                     + fabsf(a0.z - v0.z) + fabsf(a0.w - v0.w);
            float s1 = fabsf(a1.x - v1.x) + fabsf(a1.y - v1.y)
                     + fabsf(a1.z - v1.z) + fabsf(a1.w - v1.w);
            float s2 = fabsf(a2.x - v2.x) + fabsf(a2.y - v2.y)
                     + fabsf(a2.z - v2.z) + fabsf(a2.w - v2.w);
            float s3 = fabsf(a3.x - v3.x) + fabsf(a3.y - v3.y)
                     + fabsf(a3.z - v3.z) + fabsf(a3.w - v3.w);
            float s = (s0 + s1) + (s2 + s3);
            f += __expf(-s);
        }
    }

    out[(size_t)b * OUT_COLS + INPUT_DIM + k] = f;
}

extern "C" void kernel_launch(void* const* d_in, const int* in_sizes, int n_in,
                              void* d_out, int out_size)
{
    (void)in_sizes; (void)n_in; (void)out_size;
    const float* x = (const float*)d_in[0];
    const float* W = (const float*)d_in[1];
    float* out = (float*)d_out;

    mbd_gemm_kernel<<<dim3(NB_K, BATCH / 64), 256>>>(x, W);
    mbd_pairwise_kernel<<<dim3(NB_K, BATCH / 256), 256>>>(x, out);
}

// round 9
// speedup vs baseline: 1.2574x; 1.2574x over previous
#include <cuda_runtime.h>

#define BATCH      1024
#define INPUT_DIM  1024
#define NB_K       32
#define KDIM       16
#define OUT_COLS   (INPUT_DIM + NB_K)   // 1056
#define DSPLIT     8
#define DCHUNK     (INPUT_DIM / DSPLIT) // 128

__device__ float g_part[(size_t)DSPLIT * NB_K * BATCH * KDIM];  // 16 MB (L2-resident)
__device__ float g_act [(size_t)NB_K * BATCH * KDIM];           // 2 MB

// ---- packed f32x2 helpers (GEMM only — proven win there) ------------------
#define FMA_F32X2(d, a, b, c) \
    asm("fma.rn.f32x2 %0, %1, %2, %3;" : "=l"(d) : "l"(a), "l"(b), "l"(c))
#define PACK_F32X2(d, lo, hi) \
    asm("mov.b64 %0, {%1, %2};" : "=l"(d) : "f"(lo), "f"(hi))
#define UNPACK_F32X2(lo, hi, v) \
    asm("mov.b64 {%0, %1}, %2;" : "=f"(lo), "=f"(hi) : "l"(v))

// ---------------------------------------------------------------------------
// Kernel A: partial GEMM over one d-chunk of 128.  (verified 41.4us @ R7)
// grid = (32 k, 4 b-tiles of 256, 8 d-splits) = 1024 blocks, block = 256.
// ---------------------------------------------------------------------------
__global__ void __launch_bounds__(256) mbd_gemm_kernel(
    const float* __restrict__ x, const float* __restrict__ W)
{
    const int k     = blockIdx.x;
    const int b0    = blockIdx.y * 256;
    const int dbase = blockIdx.z * DCHUNK;
    const int tid   = threadIdx.x;
    const int bl    = tid & 127;
    const int h     = tid >> 7;

    __shared__ float sx[256][33];
    __shared__ float sw[32][16];

    unsigned long long accA0 = 0ull, accA1 = 0ull, accA2 = 0ull, accA3 = 0ull;
    unsigned long long accB0 = 0ull, accB1 = 0ull, accB2 = 0ull, accB3 = 0ull;

    const float4* x4 = reinterpret_cast<const float4*>(x);

    for (int d0 = dbase; d0 < dbase + DCHUNK; d0 += 32) {
#pragma unroll
        for (int i = 0; i < 8; i++) {
            int idx = tid + i * 256;
            int r = idx >> 3;
            int c = idx & 7;
            float4 v = x4[(size_t)(b0 + r) * (INPUT_DIM / 4) + (d0 >> 2) + c];
            sx[r][c * 4 + 0] = v.x;
            sx[r][c * 4 + 1] = v.y;
            sx[r][c * 4 + 2] = v.z;
            sx[r][c * 4 + 3] = v.w;
        }
        if (tid < 128) {
            const float4* w4 = reinterpret_cast<const float4*>(
                W + (size_t)k * INPUT_DIM * KDIM + (size_t)d0 * KDIM);
            reinterpret_cast<float4*>(&sw[0][0])[tid] = w4[tid];
        }
        __syncthreads();

#pragma unroll
        for (int dd = 0; dd < 32; dd++) {
            float xa = sx[bl][dd];
            float xb = sx[bl + 128][dd];
            unsigned long long xxa, xxb;
            PACK_F32X2(xxa, xa, xa);
            PACK_F32X2(xxb, xb, xb);
            const ulonglong2* wp = reinterpret_cast<const ulonglong2*>(&sw[dd][h * 8]);
            ulonglong2 wlo = wp[0];
            ulonglong2 whi = wp[1];
            FMA_F32X2(accA0, wlo.x, xxa, accA0);
            FMA_F32X2(accA1, wlo.y, xxa, accA1);
            FMA_F32X2(accA2, whi.x, xxa, accA2);
            FMA_F32X2(accA3, whi.y, xxa, accA3);
            FMA_F32X2(accB0, wlo.x, xxb, accB0);
            FMA_F32X2(accB1, wlo.y, xxb, accB1);
            FMA_F32X2(accB2, whi.x, xxb, accB2);
            FMA_F32X2(accB3, whi.y, xxb, accB3);
        }
        __syncthreads();
    }

    float* base = g_part + ((size_t)blockIdx.z * NB_K + k) * BATCH * KDIM;
    {
        float r0, r1, r2, r3, r4, r5, r6, r7;
        UNPACK_F32X2(r0, r1, accA0); UNPACK_F32X2(r2, r3, accA1);
        UNPACK_F32X2(r4, r5, accA2); UNPACK_F32X2(r6, r7, accA3);
        float4* o4 = reinterpret_cast<float4*>(
            base + (size_t)(b0 + bl) * KDIM + h * 8);
        o4[0] = make_float4(r0, r1, r2, r3);
        o4[1] = make_float4(r4, r5, r6, r7);
    }
    {
        float r0, r1, r2, r3, r4, r5, r6, r7;
        UNPACK_F32X2(r0, r1, accB0); UNPACK_F32X2(r2, r3, accB1);
        UNPACK_F32X2(r4, r5, accB2); UNPACK_F32X2(r6, r7, accB3);
        float4* o4 = reinterpret_cast<float4*>(
            base + (size_t)(b0 + bl + 128) * KDIM + h * 8);
        o4[0] = make_float4(r0, r1, r2, r3);
        o4[1] = make_float4(r4, r5, r6, r7);
    }
}

// ---------------------------------------------------------------------------
// Kernel A2: g_act = sum over the 8 d-split partials (L2-resident).
// ---------------------------------------------------------------------------
__global__ void __launch_bounds__(256) mbd_reduce_kernel()
{
    const size_t n4 = (size_t)NB_K * BATCH * KDIM / 4;   // 131072
    size_t i = (size_t)blockIdx.x * 256 + threadIdx.x;
    if (i >= n4) return;
    const float4* p = reinterpret_cast<const float4*>(g_part);
    float4 s = p[i];
#pragma unroll
    for (int z = 1; z < DSPLIT; z++) {
        float4 t = p[i + (size_t)z * n4];
        s.x += t.x; s.y += t.y; s.z += t.z; s.w += t.w;
    }
    reinterpret_cast<float4*>(g_act)[i] = s;
}

// ---------------------------------------------------------------------------
// Kernel B: feat[b][k] = sum_c exp(-sum_m |act[k][b][m] - act[k][c][m]|)
// grid = (32 k, 8 b-tiles of 128) = 256 blocks, block 256:
//   thread t -> b = b0 + (t & 127); half h = t >> 7 sums c in [512h, 512h+512).
// Full 1024-row slice staged ONCE in 64KB dynamic smem (no re-staging, one
// sync). Scalar math: abs folds into FADD src modifiers (verified fastest).
// ---------------------------------------------------------------------------
extern __shared__ float4 sa_dyn[];   // 1024 rows x 4 float4 = 64 KB

__global__ void __launch_bounds__(256) mbd_pairwise_kernel(float* __restrict__ out)
{
    const int k   = blockIdx.x;
    const int tid = threadIdx.x;
    const int bl  = tid & 127;
    const int h   = tid >> 7;
    const int b   = blockIdx.y * 128 + bl;

    __shared__ float sred[256];

    const float4* actk = reinterpret_cast<const float4*>(
        g_act + (size_t)k * BATCH * KDIM);

    // stage full slice: 4096 float4 / 256 threads = 16 each
#pragma unroll
    for (int i = 0; i < 16; i++)
        sa_dyn[tid + i * 256] = actk[tid + i * 256];
    __syncthreads();

    // my activation row (from smem — global slice already staged)
    float4 a0 = sa_dyn[b * 4 + 0];
    float4 a1 = sa_dyn[b * 4 + 1];
    float4 a2 = sa_dyn[b * 4 + 2];
    float4 a3 = sa_dyn[b * 4 + 3];

    float f = 0.f;
    const int c_beg = h * 512;
    const int c_end = c_beg + 512;

#pragma unroll 4
    for (int c = c_beg; c < c_end; c++) {
        float4 v0 = sa_dyn[c * 4 + 0];
        float4 v1 = sa_dyn[c * 4 + 1];
        float4 v2 = sa_dyn[c * 4 + 2];
        float4 v3 = sa_dyn[c * 4 + 3];
        float s0 = fabsf(a0.x - v0.x) + fabsf(a0.y - v0.y)
                 + fabsf(a0.z - v0.z) + fabsf(a0.w - v0.w);
        float s1 = fabsf(a1.x - v1.x) + fabsf(a1.y - v1.y)
                 + fabsf(a1.z - v1.z) + fabsf(a1.w - v1.w);
        float s2 = fabsf(a2.x - v2.x) + fabsf(a2.y - v2.y)
                 + fabsf(a2.z - v2.z) + fabsf(a2.w - v2.w);
        float s3 = fabsf(a3.x - v3.x) + fabsf(a3.y - v3.y)
                 + fabsf(a3.z - v3.z) + fabsf(a3.w - v3.w);
        float s = (s0 + s1) + (s2 + s3);
        f += __expf(-s);
    }

    // combine the two c-halves of each b
    sred[tid] = f;
    __syncthreads();
    if (h == 0)
        out[(size_t)b * OUT_COLS + INPUT_DIM + k] = f + sred[tid + 128];
}

// ---------------------------------------------------------------------------
// Kernel C: copy x into out[:, 0:1024] (float4) — verified 5.2us standalone.
// ---------------------------------------------------------------------------
__global__ void __launch_bounds__(256) mbd_copy_kernel(
    const float* __restrict__ x, float* __restrict__ out)
{
    const float4* x4 = reinterpret_cast<const float4*>(x);
    float4*       o4 = reinterpret_cast<float4*>(out);
    int idx0 = blockIdx.x * 256 + threadIdx.x;
    const int stride = gridDim.x * 256;
    const int n4 = BATCH * (INPUT_DIM / 4);          // 262144
#pragma unroll 4
    for (int idx = idx0; idx < n4; idx += stride) {
        int bRow = idx >> 8;
        int j    = idx & 255;
        o4[(size_t)bRow * (OUT_COLS / 4) + j] = x4[idx];
    }
}

extern "C" void kernel_launch(void* const* d_in, const int* in_sizes, int n_in,
                              void* d_out, int out_size)
{
    (void)in_sizes; (void)n_in; (void)out_size;
    const float* x = (const float*)d_in[0];
    const float* W = (const float*)d_in[1];
    float* out = (float*)d_out;

    static const int smem_bytes = BATCH * KDIM * (int)sizeof(float);  // 64 KB
    cudaFuncSetAttribute(mbd_pairwise_kernel,
                         cudaFuncAttributeMaxDynamicSharedMemorySize, smem_bytes);

    mbd_gemm_kernel<<<dim3(NB_K, BATCH / 256, DSPLIT), 256>>>(x, W);
    mbd_reduce_kernel<<<(NB_K * BATCH * KDIM / 4 + 255) / 256, 256>>>();
    mbd_pairwise_kernel<<<dim3(NB_K, BATCH / 128), 256, smem_bytes>>>(out);
    mbd_copy_kernel<<<256, 256>>>(x, out);
}

// round 10
// speedup vs baseline: 1.4259x; 1.1340x over previous
#include <cuda_runtime.h>

#define BATCH      1024
#define INPUT_DIM  1024
#define NB_K       32
#define KDIM       16
#define OUT_COLS   (INPUT_DIM + NB_K)   // 1056
#define DSPLIT     8
#define DCHUNK     (INPUT_DIM / DSPLIT) // 128
#define NTILE      8                    // 8 b-tiles of 128
#define NPAIRS     36                   // i<=j tile pairs

__device__ float g_part[(size_t)DSPLIT * NB_K * BATCH * KDIM];  // 16 MB
__device__ float g_act [(size_t)NB_K * BATCH * KDIM];           // 2 MB
// per-(k, tile i, tile j) partial feature sums; every slot written exactly once
__device__ float g_pp[(size_t)NB_K * NTILE * NTILE * 128];      // 1 MB

__constant__ int2 c_pairs[NPAIRS] = {
    {0,0},{0,1},{0,2},{0,3},{0,4},{0,5},{0,6},{0,7},
          {1,1},{1,2},{1,3},{1,4},{1,5},{1,6},{1,7},
                {2,2},{2,3},{2,4},{2,5},{2,6},{2,7},
                      {3,3},{3,4},{3,5},{3,6},{3,7},
                            {4,4},{4,5},{4,6},{4,7},
                                  {5,5},{5,6},{5,7},
                                        {6,6},{6,7},
                                              {7,7}
};

// ---- packed f32x2 helpers (GEMM only — proven win there) ------------------
#define FMA_F32X2(d, a, b, c) \
    asm("fma.rn.f32x2 %0, %1, %2, %3;" : "=l"(d) : "l"(a), "l"(b), "l"(c))
#define PACK_F32X2(d, lo, hi) \
    asm("mov.b64 %0, {%1, %2};" : "=l"(d) : "f"(lo), "f"(hi))
#define UNPACK_F32X2(lo, hi, v) \
    asm("mov.b64 {%0, %1}, %2;" : "=f"(lo), "=f"(hi) : "l"(v))

// ---------------------------------------------------------------------------
// Kernel A: partial GEMM over one d-chunk of 128.  (verified 41.4us)
// grid = (32 k, 4 b-tiles of 256, 8 d-splits) = 1024 blocks, block = 256.
// ---------------------------------------------------------------------------
__global__ void __launch_bounds__(256) mbd_gemm_kernel(
    const float* __restrict__ x, const float* __restrict__ W)
{
    const int k     = blockIdx.x;
    const int b0    = blockIdx.y * 256;
    const int dbase = blockIdx.z * DCHUNK;
    const int tid   = threadIdx.x;
    const int bl    = tid & 127;
    const int h     = tid >> 7;

    __shared__ float sx[256][33];
    __shared__ float sw[32][16];

    unsigned long long accA0 = 0ull, accA1 = 0ull, accA2 = 0ull, accA3 = 0ull;
    unsigned long long accB0 = 0ull, accB1 = 0ull, accB2 = 0ull, accB3 = 0ull;

    const float4* x4 = reinterpret_cast<const float4*>(x);

    for (int d0 = dbase; d0 < dbase + DCHUNK; d0 += 32) {
#pragma unroll
        for (int i = 0; i < 8; i++) {
            int idx = tid + i * 256;
            int r = idx >> 3;
            int c = idx & 7;
            float4 v = x4[(size_t)(b0 + r) * (INPUT_DIM / 4) + (d0 >> 2) + c];
            sx[r][c * 4 + 0] = v.x;
            sx[r][c * 4 + 1] = v.y;
            sx[r][c * 4 + 2] = v.z;
            sx[r][c * 4 + 3] = v.w;
        }
        if (tid < 128) {
            const float4* w4 = reinterpret_cast<const float4*>(
                W + (size_t)k * INPUT_DIM * KDIM + (size_t)d0 * KDIM);
            reinterpret_cast<float4*>(&sw[0][0])[tid] = w4[tid];
        }
        __syncthreads();

#pragma unroll
        for (int dd = 0; dd < 32; dd++) {
            float xa = sx[bl][dd];
            float xb = sx[bl + 128][dd];
            unsigned long long xxa, xxb;
            PACK_F32X2(xxa, xa, xa);
            PACK_F32X2(xxb, xb, xb);
            const ulonglong2* wp = reinterpret_cast<const ulonglong2*>(&sw[dd][h * 8]);
            ulonglong2 wlo = wp[0];
            ulonglong2 whi = wp[1];
            FMA_F32X2(accA0, wlo.x, xxa, accA0);
            FMA_F32X2(accA1, wlo.y, xxa, accA1);
            FMA_F32X2(accA2, whi.x, xxa, accA2);
            FMA_F32X2(accA3, whi.y, xxa, accA3);
            FMA_F32X2(accB0, wlo.x, xxb, accB0);
            FMA_F32X2(accB1, wlo.y, xxb, accB1);
            FMA_F32X2(accB2, whi.x, xxb, accB2);
            FMA_F32X2(accB3, whi.y, xxb, accB3);
        }
        __syncthreads();
    }

    float* base = g_part + ((size_t)blockIdx.z * NB_K + k) * BATCH * KDIM;
    {
        float r0, r1, r2, r3, r4, r5, r6, r7;
        UNPACK_F32X2(r0, r1, accA0); UNPACK_F32X2(r2, r3, accA1);
        UNPACK_F32X2(r4, r5, accA2); UNPACK_F32X2(r6, r7, accA3);
        float4* o4 = reinterpret_cast<float4*>(
            base + (size_t)(b0 + bl) * KDIM + h * 8);
        o4[0] = make_float4(r0, r1, r2, r3);
        o4[1] = make_float4(r4, r5, r6, r7);
    }
    {
        float r0, r1, r2, r3, r4, r5, r6, r7;
        UNPACK_F32X2(r0, r1, accB0); UNPACK_F32X2(r2, r3, accB1);
        UNPACK_F32X2(r4, r5, accB2); UNPACK_F32X2(r6, r7, accB3);
        float4* o4 = reinterpret_cast<float4*>(
            base + (size_t)(b0 + bl + 128) * KDIM + h * 8);
        o4[0] = make_float4(r0, r1, r2, r3);
        o4[1] = make_float4(r4, r5, r6, r7);
    }
}

// ---------------------------------------------------------------------------
// Kernel A2: g_act = sum over the 8 d-split partials (L2-resident).
// ---------------------------------------------------------------------------
__global__ void __launch_bounds__(256) mbd_reduce_kernel()
{
    const size_t n4 = (size_t)NB_K * BATCH * KDIM / 4;   // 131072
    size_t i = (size_t)blockIdx.x * 256 + threadIdx.x;
    if (i >= n4) return;
    const float4* p = reinterpret_cast<const float4*>(g_part);
    float4 s = p[i];
#pragma unroll
    for (int z = 1; z < DSPLIT; z++) {
        float4 t = p[i + (size_t)z * n4];
        s.x += t.x; s.y += t.y; s.z += t.z; s.w += t.w;
    }
    reinterpret_cast<float4*>(g_act)[i] = s;
}

// ---------------------------------------------------------------------------
// Kernel B: symmetric pairwise. grid = (32 k, 36 tile-pairs), block = 256.
// Pair (i,j), i<=j: rows from tile i (sA), cols from tile j (sB).
// Warp w: b-subtile (w&3) -> rows [(w&3)*32, +32); c-half (w>>2) -> 64 c's.
// Per c-step: e = exp(-L1(a, v)); f += e (row sum); warp shfl-reduce e ->
// scol (col sum, skipped on diagonal). Partials to g_pp:
//   row partial of pair (i,j) -> g_pp[k][i][j][bl]
//   col partial of pair (i,j) -> g_pp[k][j][i][c]     (i<j only)
// Every slot [k][t][u] written exactly once; assembly is a fixed-order sum.
// ---------------------------------------------------------------------------
__global__ void __launch_bounds__(256) mbd_pairwise_kernel()
{
    const int k   = blockIdx.x;
    const int tid = threadIdx.x;
    const int lane = tid & 31;
    const int w    = tid >> 5;
    const int bsub = w & 3;
    const int ch   = w >> 2;
    const int2 pr  = c_pairs[blockIdx.y];
    const int i_t  = pr.x, j_t = pr.y;
    const bool diag = (i_t == j_t);

    __shared__ float4 sA[128 * 4];      // tile i rows: 8 KB
    __shared__ float4 sB[128 * 4];      // tile j rows: 8 KB
    __shared__ float  scol[8][64];      // per-warp col partials: 2 KB
    __shared__ float  srow[256];

    const float4* actk = reinterpret_cast<const float4*>(
        g_act + (size_t)k * BATCH * KDIM);

    // stage both tiles (512 float4 each, 2 per thread per tile)
#pragma unroll
    for (int q = 0; q < 2; q++) {
        sA[tid + q * 256] = actk[(size_t)i_t * 512 + tid + q * 256];
        sB[tid + q * 256] = actk[(size_t)j_t * 512 + tid + q * 256];
    }
    // zero col accumulators (2 per thread)
    reinterpret_cast<float*>(scol)[tid]       = 0.f;
    reinterpret_cast<float*>(scol)[tid + 256] = 0.f;
    __syncthreads();

    const int bl = bsub * 32 + lane;    // row within tile i
    float4 a0 = sA[bl * 4 + 0];
    float4 a1 = sA[bl * 4 + 1];
    float4 a2 = sA[bl * 4 + 2];
    float4 a3 = sA[bl * 4 + 3];

    float f = 0.f;
    const int c_beg = ch * 64;

#pragma unroll 4
    for (int cc = 0; cc < 64; cc++) {
        const int c = c_beg + cc;
        float4 v0 = sB[c * 4 + 0];
        float4 v1 = sB[c * 4 + 1];
        float4 v2 = sB[c * 4 + 2];
        float4 v3 = sB[c * 4 + 3];
        float s0 = fabsf(a0.x - v0.x) + fabsf(a0.y - v0.y)
                 + fabsf(a0.z - v0.z) + fabsf(a0.w - v0.w);
        float s1 = fabsf(a1.x - v1.x) + fabsf(a1.y - v1.y)
                 + fabsf(a1.z - v1.z) + fabsf(a1.w - v1.w);
        float s2 = fabsf(a2.x - v2.x) + fabsf(a2.y - v2.y)
                 + fabsf(a2.z - v2.z) + fabsf(a2.w - v2.w);
        float s3 = fabsf(a3.x - v3.x) + fabsf(a3.y - v3.y)
                 + fabsf(a3.z - v3.z) + fabsf(a3.w - v3.w);
        float s = (s0 + s1) + (s2 + s3);
        float e = __expf(-s);
        f += e;

        if (!diag) {
            // column sum over the warp's 32 rows
            float es = e;
            es += __shfl_xor_sync(0xffffffffu, es, 16);
            es += __shfl_xor_sync(0xffffffffu, es, 8);
            es += __shfl_xor_sync(0xffffffffu, es, 4);
            es += __shfl_xor_sync(0xffffffffu, es, 2);
            es += __shfl_xor_sync(0xffffffffu, es, 1);
            if (lane == 0) scol[w][cc] += es;
        }
    }

    srow[tid] = f;
    __syncthreads();

    // row partials: combine the two c-halves of each row
    if (tid < 128) {
        float rt = srow[tid] + srow[tid + 128];
        g_pp[(((size_t)k * NTILE + i_t) * NTILE + j_t) * 128 + tid] = rt;
    }
    // col partials (off-diagonal only): combine the 4 b-subtile warps
    if (!diag && tid < 128) {
        const int c = tid;
        const int cch = c >> 6;
        const int cl  = c & 63;
        float ct = scol[cch * 4 + 0][cl] + scol[cch * 4 + 1][cl]
                 + scol[cch * 4 + 2][cl] + scol[cch * 4 + 3][cl];
        g_pp[(((size_t)k * NTILE + j_t) * NTILE + i_t) * 128 + c] = ct;
    }
}

// ---------------------------------------------------------------------------
// Kernel C: copy x into out[:, 0:1024]  AND  assemble features from g_pp.
// grid 256 x 256 threads. First 32768 threads also assemble one (k,b) each.
// ---------------------------------------------------------------------------
__global__ void __launch_bounds__(256) mbd_copy_kernel(
    const float* __restrict__ x, float* __restrict__ out)
{
    const int gtid = blockIdx.x * 256 + threadIdx.x;

    // feature assembly: 32 k x 1024 b = 32768 outputs
    if (gtid < NB_K * BATCH) {
        const int k = gtid >> 10;
        const int b = gtid & 1023;
        const int t = b >> 7;
        const int r = b & 127;
        const float* pp = g_pp + (((size_t)k * NTILE + t) * NTILE) * 128 + r;
        float s = 0.f;
#pragma unroll
        for (int j = 0; j < NTILE; j++)
            s += pp[j * 128];
        out[(size_t)b * OUT_COLS + INPUT_DIM + k] = s;
    }

    // x copy (float4)
    const float4* x4 = reinterpret_cast<const float4*>(x);
    float4*       o4 = reinterpret_cast<float4*>(out);
    const int n4 = BATCH * (INPUT_DIM / 4);          // 262144
    const int stride = gridDim.x * 256;
#pragma unroll 4
    for (int idx = gtid; idx < n4; idx += stride) {
        int bRow = idx >> 8;
        int j    = idx & 255;
        o4[(size_t)bRow * (OUT_COLS / 4) + j] = x4[idx];
    }
}

extern "C" void kernel_launch(void* const* d_in, const int* in_sizes, int n_in,
                              void* d_out, int out_size)
{
    (void)in_sizes; (void)n_in; (void)out_size;
    const float* x = (const float*)d_in[0];
    const float* W = (const float*)d_in[1];
    float* out = (float*)d_out;

    mbd_gemm_kernel<<<dim3(NB_K, BATCH / 256, DSPLIT), 256>>>(x, W);
    mbd_reduce_kernel<<<(NB_K * BATCH * KDIM / 4 + 255) / 256, 256>>>();
    mbd_pairwise_kernel<<<dim3(NB_K, NPAIRS), 256>>>();
    mbd_copy_kernel<<<256, 256>>>(x, out);
}

// round 11
// speedup vs baseline: 1.6357x; 1.1471x over previous
#include <cuda_runtime.h>
#include <cuda_bf16.h>

#define BATCH      1024
#define INPUT_DIM  1024
#define NB_K       32
#define KDIM       16
#define OUT_COLS   (INPUT_DIM + NB_K)   // 1056
#define NTILE      8                    // 8 b-tiles of 128 (pairwise)
#define NPAIRS     36                   // i<=j tile pairs

__device__ float        g_act[(size_t)NB_K * BATCH * KDIM];        // 2 MB
__device__ float        g_pp [(size_t)NB_K * NTILE * NTILE * 128]; // 1 MB
__device__ unsigned int g_xbf [(size_t)BATCH * INPUT_DIM / 2];     // x bf16: [1024][512] uint
__device__ unsigned int g_wtbf[(size_t)NB_K * KDIM * INPUT_DIM / 2]; // Wt bf16: [32][16][512] uint

__constant__ int2 c_pairs[NPAIRS] = {
    {0,0},{0,1},{0,2},{0,3},{0,4},{0,5},{0,6},{0,7},
          {1,1},{1,2},{1,3},{1,4},{1,5},{1,6},{1,7},
                {2,2},{2,3},{2,4},{2,5},{2,6},{2,7},
                      {3,3},{3,4},{3,5},{3,6},{3,7},
                            {4,4},{4,5},{4,6},{4,7},
                                  {5,5},{5,6},{5,7},
                                        {6,6},{6,7},
                                              {7,7}
};

#define MMA_BF16(c0,c1,c2,c3,a0,a1,a2,a3,b0,b1) \
    asm("mma.sync.aligned.m16n8k16.row.col.f32.bf16.bf16.f32 " \
        "{%0,%1,%2,%3}, {%4,%5,%6,%7}, {%8,%9}, {%0,%1,%2,%3};" \
        : "+f"(c0), "+f"(c1), "+f"(c2), "+f"(c3) \
        : "r"(a0), "r"(a1), "r"(a2), "r"(a3), "r"(b0), "r"(b1))

// ---------------------------------------------------------------------------
// Kernel 0: convert. blocks 0..31: W[k][d][m] -> Wt_bf16[k][m][d] (transpose).
//           blocks 32..159: x fp32 -> x_bf16 (8 rows per block).
// ---------------------------------------------------------------------------
__global__ void __launch_bounds__(256) mbd_convert_kernel(
    const float* __restrict__ x, const float* __restrict__ W)
{
    __shared__ unsigned short swt[16 * 1024];   // 32 KB (W-transpose blocks only)
    const int tid = threadIdx.x;

    if (blockIdx.x < NB_K) {
        const int k = blockIdx.x;
        const float4* wk4 = reinterpret_cast<const float4*>(
            W + (size_t)k * INPUT_DIM * KDIM);
#pragma unroll
        for (int i = 0; i < 16; i++) {
            int idx = tid + i * 256;            // float4 index, 4096 total
            int base = idx * 4;
            int d = base >> 4;
            int m = base & 15;                  // {0,4,8,12}
            float4 v = wk4[idx];
            swt[(m + 0) * 1024 + d] = __bfloat16_as_ushort(__float2bfloat16(v.x));
            swt[(m + 1) * 1024 + d] = __bfloat16_as_ushort(__float2bfloat16(v.y));
            swt[(m + 2) * 1024 + d] = __bfloat16_as_ushort(__float2bfloat16(v.z));
            swt[(m + 3) * 1024 + d] = __bfloat16_as_ushort(__float2bfloat16(v.w));
        }
        __syncthreads();
        unsigned int* o = g_wtbf + (size_t)k * 8192;
        const unsigned int* s = reinterpret_cast<const unsigned int*>(swt);
#pragma unroll
        for (int i = 0; i < 32; i++)
            o[tid + i * 256] = s[tid + i * 256];
    } else {
        const int bx = blockIdx.x - NB_K;       // 0..127
        const int base_row = bx * 8;
        const float4* x4 = reinterpret_cast<const float4*>(x);
        uint2* o2 = reinterpret_cast<uint2*>(g_xbf);
#pragma unroll
        for (int i = 0; i < 8; i++) {
            int idx = tid + i * 256;            // 0..2047: 8 rows x 256 float4
            int r = idx >> 8;
            int c = idx & 255;
            float4 v = x4[(size_t)(base_row + r) * 256 + c];
            __nv_bfloat162 lo = __floats2bfloat162_rn(v.x, v.y);
            __nv_bfloat162 hi = __floats2bfloat162_rn(v.z, v.w);
            uint2 o;
            o.x = *reinterpret_cast<unsigned int*>(&lo);
            o.y = *reinterpret_cast<unsigned int*>(&hi);
            o2[(size_t)(base_row + r) * 256 + c] = o;
        }
    }
}

// ---------------------------------------------------------------------------
// Kernel A: tensor-core GEMM. act[k][b][m] = sum_d x[b][d] * W[k][d][m].
// grid = (8 k-groups, 64 b-tiles of 16) = 512 blocks, block = 128 (4 warps).
// Warp w handles k = blockIdx.x*4 + w on the shared 16-row x tile (smem bf16,
// pitch 516 uints = conflict-free). B (Wt bf16) streamed from L2.
// Per k16-step: 4 LDS.32 (A) + 4 LDG.32 (B) + 2 HMMA.
// ---------------------------------------------------------------------------
__global__ void __launch_bounds__(128) mbd_gemm_kernel()
{
    __shared__ unsigned int sxs[16 * 516];      // 33 KB, pitch 516 uints/row

    const int tid  = threadIdx.x;
    const int lane = tid & 31;
    const int w    = tid >> 5;
    const int k    = blockIdx.x * 4 + w;
    const int b0   = blockIdx.y * 16;
    const int g    = lane >> 2;                 // groupID 0..7
    const int tig  = lane & 3;                  // thread-in-group

    // stage x tile: 16 rows x 256 uint2, 32 per thread
    {
        const uint2* xr = reinterpret_cast<const uint2*>(g_xbf);
#pragma unroll
        for (int i = 0; i < 32; i++) {
            int idx = tid + i * 128;            // 0..4095
            int r = idx >> 8;
            int c = idx & 255;
            uint2 v = xr[(size_t)(b0 + r) * 256 + c];
            *reinterpret_cast<uint2*>(sxs + r * 516 + 2 * c) = v;
        }
    }
    __syncthreads();

    float c0 = 0.f, c1 = 0.f, c2 = 0.f, c3 = 0.f;   // n-half 0
    float c4 = 0.f, c5 = 0.f, c6 = 0.f, c7 = 0.f;   // n-half 1

    const unsigned int* bw = g_wtbf + (size_t)k * 8192;  // [16 n][512 d-uints]
    const int ia_base = g * 516 + tig;
    const int ib_base = g * 512 + tig;

#pragma unroll 4
    for (int d0 = 0; d0 < 512; d0 += 8) {       // 8 uints = 16 bf16 per step
        unsigned int a0 = sxs[ia_base + d0];
        unsigned int a1 = sxs[ia_base + d0 + 8 * 516];
        unsigned int a2 = sxs[ia_base + d0 + 4];
        unsigned int a3 = sxs[ia_base + d0 + 4 + 8 * 516];
        unsigned int b00 = bw[ib_base + d0];
        unsigned int b01 = bw[ib_base + d0 + 4];
        unsigned int b10 = bw[ib_base + d0 + 8 * 512];
        unsigned int b11 = bw[ib_base + d0 + 8 * 512 + 4];
        MMA_BF16(c0, c1, c2, c3, a0, a1, a2, a3, b00, b01);
        MMA_BF16(c4, c5, c6, c7, a0, a1, a2, a3, b10, b11);
    }

    // write 16x16 result: C[g][tig*2..+1] (+8 rows, +8 cols variants)
    float* orow  = g_act + ((size_t)k * BATCH + b0 + g) * KDIM;
    float* orow2 = orow + 8 * KDIM;
    *reinterpret_cast<float2*>(orow  + tig * 2)     = make_float2(c0, c1);
    *reinterpret_cast<float2*>(orow  + 8 + tig * 2) = make_float2(c4, c5);
    *reinterpret_cast<float2*>(orow2 + tig * 2)     = make_float2(c2, c3);
    *reinterpret_cast<float2*>(orow2 + 8 + tig * 2) = make_float2(c6, c7);
}

// ---------------------------------------------------------------------------
// Kernel B: symmetric pairwise (verified R10). grid = (32 k, 36 tile-pairs).
// ---------------------------------------------------------------------------
__global__ void __launch_bounds__(256) mbd_pairwise_kernel()
{
    const int k   = blockIdx.x;
    const int tid = threadIdx.x;
    const int lane = tid & 31;
    const int w    = tid >> 5;
    const int bsub = w & 3;
    const int ch   = w >> 2;
    const int2 pr  = c_pairs[blockIdx.y];
    const int i_t  = pr.x, j_t = pr.y;
    const bool diag = (i_t == j_t);

    __shared__ float4 sA[128 * 4];
    __shared__ float4 sB[128 * 4];
    __shared__ float  scol[8][64];
    __shared__ float  srow[256];

    const float4* actk = reinterpret_cast<const float4*>(
        g_act + (size_t)k * BATCH * KDIM);

#pragma unroll
    for (int q = 0; q < 2; q++) {
        sA[tid + q * 256] = actk[(size_t)i_t * 512 + tid + q * 256];
        sB[tid + q * 256] = actk[(size_t)j_t * 512 + tid + q * 256];
    }
    reinterpret_cast<float*>(scol)[tid]       = 0.f;
    reinterpret_cast<float*>(scol)[tid + 256] = 0.f;
    __syncthreads();

    const int bl = bsub * 32 + lane;
    float4 a0 = sA[bl * 4 + 0];
    float4 a1 = sA[bl * 4 + 1];
    float4 a2 = sA[bl * 4 + 2];
    float4 a3 = sA[bl * 4 + 3];

    float f = 0.f;
    const int c_beg = ch * 64;

#pragma unroll 4
    for (int cc = 0; cc < 64; cc++) {
        const int c = c_beg + cc;
        float4 v0 = sB[c * 4 + 0];
        float4 v1 = sB[c * 4 + 1];
        float4 v2 = sB[c * 4 + 2];
        float4 v3 = sB[c * 4 + 3];
        float s0 = fabsf(a0.x - v0.x) + fabsf(a0.y - v0.y)
                 + fabsf(a0.z - v0.z) + fabsf(a0.w - v0.w);
        float s1 = fabsf(a1.x - v1.x) + fabsf(a1.y - v1.y)
                 + fabsf(a1.z - v1.z) + fabsf(a1.w - v1.w);
        float s2 = fabsf(a2.x - v2.x) + fabsf(a2.y - v2.y)
                 + fabsf(a2.z - v2.z) + fabsf(a2.w - v2.w);
        float s3 = fabsf(a3.x - v3.x) + fabsf(a3.y - v3.y)
                 + fabsf(a3.z - v3.z) + fabsf(a3.w - v3.w);
        float s = (s0 + s1) + (s2 + s3);
        float e = __expf(-s);
        f += e;

        if (!diag) {
            float es = e;
            es += __shfl_xor_sync(0xffffffffu, es, 16);
            es += __shfl_xor_sync(0xffffffffu, es, 8);
            es += __shfl_xor_sync(0xffffffffu, es, 4);
            es += __shfl_xor_sync(0xffffffffu, es, 2);
            es += __shfl_xor_sync(0xffffffffu, es, 1);
            if (lane == 0) scol[w][cc] += es;
        }
    }

    srow[tid] = f;
    __syncthreads();

    if (tid < 128) {
        float rt = srow[tid] + srow[tid + 128];
        g_pp[(((size_t)k * NTILE + i_t) * NTILE + j_t) * 128 + tid] = rt;
    }
    if (!diag && tid < 128) {
        const int c = tid;
        const int cch = c >> 6;
        const int cl  = c & 63;
        float ct = scol[cch * 4 + 0][cl] + scol[cch * 4 + 1][cl]
                 + scol[cch * 4 + 2][cl] + scol[cch * 4 + 3][cl];
        g_pp[(((size_t)k * NTILE + j_t) * NTILE + i_t) * 128 + c] = ct;
    }
}

// ---------------------------------------------------------------------------
// Kernel C: copy x into out[:, 0:1024] AND assemble features from g_pp.
// ---------------------------------------------------------------------------
__global__ void __launch_bounds__(256) mbd_copy_kernel(
    const float* __restrict__ x, float* __restrict__ out)
{
    const int gtid = blockIdx.x * 256 + threadIdx.x;

    if (gtid < NB_K * BATCH) {
        const int k = gtid >> 10;
        const int b = gtid & 1023;
        const int t = b >> 7;
        const int r = b & 127;
        const float* pp = g_pp + (((size_t)k * NTILE + t) * NTILE) * 128 + r;
        float s = 0.f;
#pragma unroll
        for (int j = 0; j < NTILE; j++)
            s += pp[j * 128];
        out[(size_t)b * OUT_COLS + INPUT_DIM + k] = s;
    }

    const float4* x4 = reinterpret_cast<const float4*>(x);
    float4*       o4 = reinterpret_cast<float4*>(out);
    const int n4 = BATCH * (INPUT_DIM / 4);
    const int stride = gridDim.x * 256;
#pragma unroll 4
    for (int idx = gtid; idx < n4; idx += stride) {
        int bRow = idx >> 8;
        int j    = idx & 255;
        o4[(size_t)bRow * (OUT_COLS / 4) + j] = x4[idx];
    }
}

extern "C" void kernel_launch(void* const* d_in, const int* in_sizes, int n_in,
                              void* d_out, int out_size)
{
    (void)in_sizes; (void)n_in; (void)out_size;
    const float* x = (const float*)d_in[0];
    const float* W = (const float*)d_in[1];
    float* out = (float*)d_out;

    mbd_convert_kernel<<<NB_K + BATCH / 8, 256>>>(x, W);
    mbd_gemm_kernel<<<dim3(NB_K / 4, BATCH / 16), 128>>>();
    mbd_pairwise_kernel<<<dim3(NB_K, NPAIRS), 256>>>();
    mbd_copy_kernel<<<256, 256>>>(x, out);
}

// round 12
// speedup vs baseline: 1.8636x; 1.1393x over previous
#include <cuda_runtime.h>
#include <cuda_bf16.h>
#include <cuda_fp16.h>

#define BATCH      1024
#define INPUT_DIM  1024
#define NB_K       32
#define KDIM       16
#define OUT_COLS   (INPUT_DIM + NB_K)   // 1056
#define NTILE      8                    // 8 b-tiles of 128 (pairwise)
#define NPAIRS     36                   // i<=j tile pairs

__device__ __half2      g_acth[(size_t)NB_K * BATCH * 8];          // 1 MB (fp16 acts)
__device__ float        g_pp  [(size_t)NB_K * NTILE * NTILE * 128]; // 1 MB
__device__ unsigned int g_wtbf[(size_t)NB_K * KDIM * INPUT_DIM / 2]; // Wt bf16: [32][16][512] uint

__constant__ int2 c_pairs[NPAIRS] = {
    {0,0},{0,1},{0,2},{0,3},{0,4},{0,5},{0,6},{0,7},
          {1,1},{1,2},{1,3},{1,4},{1,5},{1,6},{1,7},
                {2,2},{2,3},{2,4},{2,5},{2,6},{2,7},
                      {3,3},{3,4},{3,5},{3,6},{3,7},
                            {4,4},{4,5},{4,6},{4,7},
                                  {5,5},{5,6},{5,7},
                                        {6,6},{6,7},
                                              {7,7}
};

#define MMA_BF16(c0,c1,c2,c3,a0,a1,a2,a3,b0,b1) \
    asm("mma.sync.aligned.m16n8k16.row.col.f32.bf16.bf16.f32 " \
        "{%0,%1,%2,%3}, {%4,%5,%6,%7}, {%8,%9}, {%0,%1,%2,%3};" \
        : "+f"(c0), "+f"(c1), "+f"(c2), "+f"(c3) \
        : "r"(a0), "r"(a1), "r"(a2), "r"(a3), "r"(b0), "r"(b1))

// ---------------------------------------------------------------------------
// Kernel 0: W convert+transpose only. 32 blocks: W[k][d][m] -> Wt_bf16[k][m][d].
// ---------------------------------------------------------------------------
__global__ void __launch_bounds__(256) mbd_wconvert_kernel(
    const float* __restrict__ W)
{
    __shared__ unsigned short swt[16 * 1024];   // 32 KB
    const int tid = threadIdx.x;
    const int k = blockIdx.x;

    const float4* wk4 = reinterpret_cast<const float4*>(
        W + (size_t)k * INPUT_DIM * KDIM);
#pragma unroll
    for (int i = 0; i < 16; i++) {
        int idx = tid + i * 256;            // float4 index, 4096 total
        int base = idx * 4;
        int d = base >> 4;
        int m = base & 15;                  // {0,4,8,12}
        float4 v = wk4[idx];
        swt[(m + 0) * 1024 + d] = __bfloat16_as_ushort(__float2bfloat16(v.x));
        swt[(m + 1) * 1024 + d] = __bfloat16_as_ushort(__float2bfloat16(v.y));
        swt[(m + 2) * 1024 + d] = __bfloat16_as_ushort(__float2bfloat16(v.z));
        swt[(m + 3) * 1024 + d] = __bfloat16_as_ushort(__float2bfloat16(v.w));
    }
    __syncthreads();
    unsigned int* o = g_wtbf + (size_t)k * 8192;
    const unsigned int* s = reinterpret_cast<const unsigned int*>(swt);
#pragma unroll
    for (int i = 0; i < 32; i++)
        o[tid + i * 256] = s[tid + i * 256];
}

// ---------------------------------------------------------------------------
// Kernel A: tensor-core GEMM, x converted inline. Writes g_acth (fp16).
// grid = (8 k-groups, 64 b-tiles of 16) = 512 blocks, block = 128 (4 warps).
// Warp w handles k = blockIdx.x*4 + w on the shared 16-row x tile (smem bf16,
// pitch 516 uints = conflict-free). B (Wt bf16) streamed from L2.
// ---------------------------------------------------------------------------
__global__ void __launch_bounds__(128) mbd_gemm_kernel(
    const float* __restrict__ x)
{
    __shared__ unsigned int sxs[16 * 516];      // 33 KB, pitch 516 uints/row

    const int tid  = threadIdx.x;
    const int lane = tid & 31;
    const int w    = tid >> 5;
    const int k    = blockIdx.x * 4 + w;
    const int b0   = blockIdx.y * 16;
    const int g    = lane >> 2;                 // groupID 0..7
    const int tig  = lane & 3;                  // thread-in-group

    // stage x tile: read fp32, convert to bf16 inline (16 rows x 256 float4)
    {
        const float4* x4 = reinterpret_cast<const float4*>(x);
#pragma unroll
        for (int i = 0; i < 32; i++) {
            int idx = tid + i * 128;            // 0..4095
            int r = idx >> 8;
            int c = idx & 255;
            float4 v = x4[(size_t)(b0 + r) * 256 + c];
            __nv_bfloat162 lo = __floats2bfloat162_rn(v.x, v.y);
            __nv_bfloat162 hi = __floats2bfloat162_rn(v.z, v.w);
            uint2 o;
            o.x = *reinterpret_cast<unsigned int*>(&lo);
            o.y = *reinterpret_cast<unsigned int*>(&hi);
            *reinterpret_cast<uint2*>(sxs + r * 516 + 2 * c) = o;
        }
    }
    __syncthreads();

    float c0 = 0.f, c1 = 0.f, c2 = 0.f, c3 = 0.f;   // n-half 0
    float c4 = 0.f, c5 = 0.f, c6 = 0.f, c7 = 0.f;   // n-half 1

    const unsigned int* bw = g_wtbf + (size_t)k * 8192;  // [16 n][512 d-uints]
    const int ia_base = g * 516 + tig;
    const int ib_base = g * 512 + tig;

#pragma unroll 4
    for (int d0 = 0; d0 < 512; d0 += 8) {       // 8 uints = 16 bf16 per step
        unsigned int a0 = sxs[ia_base + d0];
        unsigned int a1 = sxs[ia_base + d0 + 8 * 516];
        unsigned int a2 = sxs[ia_base + d0 + 4];
        unsigned int a3 = sxs[ia_base + d0 + 4 + 8 * 516];
        unsigned int b00 = bw[ib_base + d0];
        unsigned int b01 = bw[ib_base + d0 + 4];
        unsigned int b10 = bw[ib_base + d0 + 8 * 512];
        unsigned int b11 = bw[ib_base + d0 + 8 * 512 + 4];
        MMA_BF16(c0, c1, c2, c3, a0, a1, a2, a3, b00, b01);
        MMA_BF16(c4, c5, c6, c7, a0, a1, a2, a3, b10, b11);
    }

    // write 16x16 result as fp16: row layout = 8 half2 per b-row
    __half2* o1 = g_acth + ((size_t)k * BATCH + b0 + g) * 8;
    __half2* o2 = o1 + 8 * 8;                   // +8 rows
    o1[tig]     = __float22half2_rn(make_float2(c0, c1));
    o1[4 + tig] = __float22half2_rn(make_float2(c4, c5));
    o2[tig]     = __float22half2_rn(make_float2(c2, c3));
    o2[4 + tig] = __float22half2_rn(make_float2(c6, c7));
}

// ---------------------------------------------------------------------------
// Kernel B: symmetric pairwise in half2. grid = (32 k, 36 tile-pairs).
// Structure verbatim from verified R10; math in fp16 pairs:
//   8 HSUB2 + habs2 (folds to |src|) + 7 HADD2 tree + fp32 exp/accumulate.
// ---------------------------------------------------------------------------
__global__ void __launch_bounds__(256) mbd_pairwise_kernel()
{
    const int k    = blockIdx.x;
    const int tid  = threadIdx.x;
    const int lane = tid & 31;
    const int w    = tid >> 5;
    const int bsub = w & 3;
    const int ch   = w >> 2;
    const int2 pr  = c_pairs[blockIdx.y];
    const int i_t  = pr.x, j_t = pr.y;
    const bool diag = (i_t == j_t);

    __shared__ uint4 sA[128 * 2];       // tile i rows: 4 KB (fp16)
    __shared__ uint4 sB[128 * 2];       // tile j rows: 4 KB
    __shared__ float scol[8][64];
    __shared__ float srow[256];

    const uint4* actk = reinterpret_cast<const uint4*>(
        g_acth + (size_t)k * BATCH * 8);

    // stage both tiles: 256 uint4 each, 1 per thread per tile
    sA[tid] = actk[(size_t)i_t * 256 + tid];
    sB[tid] = actk[(size_t)j_t * 256 + tid];
    reinterpret_cast<float*>(scol)[tid]       = 0.f;
    reinterpret_cast<float*>(scol)[tid + 256] = 0.f;
    __syncthreads();

    const int bl = bsub * 32 + lane;
    __half2 a[8];
    {
        uint4 p0 = sA[bl * 2 + 0];
        uint4 p1 = sA[bl * 2 + 1];
        a[0] = *reinterpret_cast<__half2*>(&p0.x);
        a[1] = *reinterpret_cast<__half2*>(&p0.y);
        a[2] = *reinterpret_cast<__half2*>(&p0.z);
        a[3] = *reinterpret_cast<__half2*>(&p0.w);
        a[4] = *reinterpret_cast<__half2*>(&p1.x);
        a[5] = *reinterpret_cast<__half2*>(&p1.y);
        a[6] = *reinterpret_cast<__half2*>(&p1.z);
        a[7] = *reinterpret_cast<__half2*>(&p1.w);
    }

    float f = 0.f;
    const int c_beg = ch * 64;

#pragma unroll 4
    for (int cc = 0; cc < 64; cc++) {
        const int c = c_beg + cc;
        uint4 p0 = sB[c * 2 + 0];
        uint4 p1 = sB[c * 2 + 1];
        __half2 h0 = __habs2(__hsub2(a[0], *reinterpret_cast<__half2*>(&p0.x)));
        __half2 h1 = __habs2(__hsub2(a[1], *reinterpret_cast<__half2*>(&p0.y)));
        __half2 h2 = __habs2(__hsub2(a[2], *reinterpret_cast<__half2*>(&p0.z)));
        __half2 h3 = __habs2(__hsub2(a[3], *reinterpret_cast<__half2*>(&p0.w)));
        __half2 h4 = __habs2(__hsub2(a[4], *reinterpret_cast<__half2*>(&p1.x)));
        __half2 h5 = __habs2(__hsub2(a[5], *reinterpret_cast<__half2*>(&p1.y)));
        __half2 h6 = __habs2(__hsub2(a[6], *reinterpret_cast<__half2*>(&p1.z)));
        __half2 h7 = __habs2(__hsub2(a[7], *reinterpret_cast<__half2*>(&p1.w)));
        __half2 t0 = __hadd2(h0, h1);
        __half2 t1 = __hadd2(h2, h3);
        __half2 t2 = __hadd2(h4, h5);
        __half2 t3 = __hadd2(h6, h7);
        t0 = __hadd2(t0, t1);
        t2 = __hadd2(t2, t3);
        t0 = __hadd2(t0, t2);
        float s = __low2float(t0) + __high2float(t0);
        float e = __expf(-s);
        f += e;

        if (!diag) {
            float es = e;
            es += __shfl_xor_sync(0xffffffffu, es, 16);
            es += __shfl_xor_sync(0xffffffffu, es, 8);
            es += __shfl_xor_sync(0xffffffffu, es, 4);
            es += __shfl_xor_sync(0xffffffffu, es, 2);
            es += __shfl_xor_sync(0xffffffffu, es, 1);
            if (lane == 0) scol[w][cc] += es;
        }
    }

    srow[tid] = f;
    __syncthreads();

    if (tid < 128) {
        float rt = srow[tid] + srow[tid + 128];
        g_pp[(((size_t)k * NTILE + i_t) * NTILE + j_t) * 128 + tid] = rt;
    }
    if (!diag && tid < 128) {
        const int c   = tid;
        const int cch = c >> 6;
        const int cl  = c & 63;
        float ct = scol[cch * 4 + 0][cl] + scol[cch * 4 + 1][cl]
                 + scol[cch * 4 + 2][cl] + scol[cch * 4 + 3][cl];
        g_pp[(((size_t)k * NTILE + j_t) * NTILE + i_t) * 128 + c] = ct;
    }
}

// ---------------------------------------------------------------------------
// Kernel C: copy x into out[:, 0:1024] AND assemble features from g_pp.
// ---------------------------------------------------------------------------
__global__ void __launch_bounds__(256) mbd_copy_kernel(
    const float* __restrict__ x, float* __restrict__ out)
{
    const int gtid = blockIdx.x * 256 + threadIdx.x;

    if (gtid < NB_K * BATCH) {
        const int k = gtid >> 10;
        const int b = gtid & 1023;
        const int t = b >> 7;
        const int r = b & 127;
        const float* pp = g_pp + (((size_t)k * NTILE + t) * NTILE) * 128 + r;
        float s = 0.f;
#pragma unroll
        for (int j = 0; j < NTILE; j++)
            s += pp[j * 128];
        out[(size_t)b * OUT_COLS + INPUT_DIM + k] = s;
    }

    const float4* x4 = reinterpret_cast<const float4*>(x);
    float4*       o4 = reinterpret_cast<float4*>(out);
    const int n4 = BATCH * (INPUT_DIM / 4);
    const int stride = gridDim.x * 256;
#pragma unroll 2
    for (int idx = gtid; idx < n4; idx += stride) {
        int bRow = idx >> 8;
        int j    = idx & 255;
        o4[(size_t)bRow * (OUT_COLS / 4) + j] = x4[idx];
    }
}

extern "C" void kernel_launch(void* const* d_in, const int* in_sizes, int n_in,
                              void* d_out, int out_size)
{
    (void)in_sizes; (void)n_in; (void)out_size;
    const float* x = (const float*)d_in[0];
    const float* W = (const float*)d_in[1];
    float* out = (float*)d_out;

    mbd_wconvert_kernel<<<NB_K, 256>>>(W);
    mbd_gemm_kernel<<<dim3(NB_K / 4, BATCH / 16), 128>>>(x);
    mbd_pairwise_kernel<<<dim3(NB_K, NPAIRS), 256>>>();
    mbd_copy_kernel<<<512, 256>>>(x, out);
}

// round 13
// speedup vs baseline: 1.9745x; 1.0595x over previous
#include <cuda_runtime.h>
#include <cuda_bf16.h>
#include <cuda_fp16.h>

#define BATCH      1024
#define INPUT_DIM  1024
#define NB_K       32
#define KDIM       16
#define OUT_COLS   (INPUT_DIM + NB_K)   // 1056
#define NTILE      8                    // 8 b-tiles of 128 (pairwise)
#define NPAIRS     36                   // i<=j tile pairs

__device__ __half2      g_acth[(size_t)NB_K * BATCH * 8];            // 1 MB
__device__ float        g_pp  [(size_t)NB_K * NTILE * NTILE * 128];  // 1 MB
__device__ unsigned int g_wtbf[(size_t)NB_K * KDIM * INPUT_DIM / 2]; // Wt bf16

__constant__ int2 c_pairs[NPAIRS] = {
    {0,0},{0,1},{0,2},{0,3},{0,4},{0,5},{0,6},{0,7},
          {1,1},{1,2},{1,3},{1,4},{1,5},{1,6},{1,7},
                {2,2},{2,3},{2,4},{2,5},{2,6},{2,7},
                      {3,3},{3,4},{3,5},{3,6},{3,7},
                            {4,4},{4,5},{4,6},{4,7},
                                  {5,5},{5,6},{5,7},
                                        {6,6},{6,7},
                                              {7,7}
};

#define MMA_BF16(c0,c1,c2,c3,a0,a1,a2,a3,b0,b1) \
    asm("mma.sync.aligned.m16n8k16.row.col.f32.bf16.bf16.f32 " \
        "{%0,%1,%2,%3}, {%4,%5,%6,%7}, {%8,%9}, {%0,%1,%2,%3};" \
        : "+f"(c0), "+f"(c1), "+f"(c2), "+f"(c3) \
        : "r"(a0), "r"(a1), "r"(a2), "r"(a3), "r"(b0), "r"(b1))

// ---------------------------------------------------------------------------
// Kernel 0: W convert+transpose. 32 blocks: W[k][d][m] -> Wt_bf16[k][m][d].
// ---------------------------------------------------------------------------
__global__ void __launch_bounds__(256) mbd_wconvert_kernel(
    const float* __restrict__ W)
{
    __shared__ unsigned short swt[16 * 1024];   // 32 KB
    const int tid = threadIdx.x;
    const int k = blockIdx.x;

    const float4* wk4 = reinterpret_cast<const float4*>(
        W + (size_t)k * INPUT_DIM * KDIM);
#pragma unroll
    for (int i = 0; i < 16; i++) {
        int idx = tid + i * 256;
        int base = idx * 4;
        int d = base >> 4;
        int m = base & 15;
        float4 v = wk4[idx];
        swt[(m + 0) * 1024 + d] = __bfloat16_as_ushort(__float2bfloat16(v.x));
        swt[(m + 1) * 1024 + d] = __bfloat16_as_ushort(__float2bfloat16(v.y));
        swt[(m + 2) * 1024 + d] = __bfloat16_as_ushort(__float2bfloat16(v.z));
        swt[(m + 3) * 1024 + d] = __bfloat16_as_ushort(__float2bfloat16(v.w));
    }
    __syncthreads();
    unsigned int* o = g_wtbf + (size_t)k * 8192;
    const unsigned int* s = reinterpret_cast<const unsigned int*>(swt);
#pragma unroll
    for (int i = 0; i < 32; i++)
        o[tid + i * 256] = s[tid + i * 256];
}

// ---------------------------------------------------------------------------
// Kernel A: tensor-core GEMM (bf16 MMA, fp32 acc -> fp16 out) + folded x-copy.
// grid = (8 k-groups, 64 b-tiles of 16) = 512 blocks, block = 128 (4 warps).
// ---------------------------------------------------------------------------
__global__ void __launch_bounds__(128) mbd_gemm_kernel(
    const float* __restrict__ x, float* __restrict__ out)
{
    __shared__ unsigned int sxs[16 * 516];      // 33 KB, pitch 516 uints/row

    const int tid  = threadIdx.x;
    const int lane = tid & 31;
    const int w    = tid >> 5;
    const int k    = blockIdx.x * 4 + w;
    const int b0   = blockIdx.y * 16;
    const int g    = lane >> 2;
    const int tig  = lane & 3;

    // ---- folded x-copy: 512 blocks x 512 float4 covers all of x ----
    {
        const int flat = blockIdx.y * 8 + blockIdx.x;    // 0..511
        const float4* x4 = reinterpret_cast<const float4*>(x);
        float4*       o4 = reinterpret_cast<float4*>(out);
#pragma unroll
        for (int i = 0; i < 4; i++) {
            int idx = flat * 512 + tid + i * 128;
            int r = idx >> 8;
            int c = idx & 255;
            o4[(size_t)r * (OUT_COLS / 4) + c] = x4[idx];
        }
    }

    // stage x tile: read fp32, convert to bf16 inline
    {
        const float4* x4 = reinterpret_cast<const float4*>(x);
#pragma unroll
        for (int i = 0; i < 32; i++) {
            int idx = tid + i * 128;
            int r = idx >> 8;
            int c = idx & 255;
            float4 v = x4[(size_t)(b0 + r) * 256 + c];
            __nv_bfloat162 lo = __floats2bfloat162_rn(v.x, v.y);
            __nv_bfloat162 hi = __floats2bfloat162_rn(v.z, v.w);
            uint2 o;
            o.x = *reinterpret_cast<unsigned int*>(&lo);
            o.y = *reinterpret_cast<unsigned int*>(&hi);
            *reinterpret_cast<uint2*>(sxs + r * 516 + 2 * c) = o;
        }
    }
    __syncthreads();

    float c0 = 0.f, c1 = 0.f, c2 = 0.f, c3 = 0.f;
    float c4 = 0.f, c5 = 0.f, c6 = 0.f, c7 = 0.f;

    const unsigned int* bw = g_wtbf + (size_t)k * 8192;
    const int ia_base = g * 516 + tig;
    const int ib_base = g * 512 + tig;

#pragma unroll 4
    for (int d0 = 0; d0 < 512; d0 += 8) {
        unsigned int a0 = sxs[ia_base + d0];
        unsigned int a1 = sxs[ia_base + d0 + 8 * 516];
        unsigned int a2 = sxs[ia_base + d0 + 4];
        unsigned int a3 = sxs[ia_base + d0 + 4 + 8 * 516];
        unsigned int b00 = bw[ib_base + d0];
        unsigned int b01 = bw[ib_base + d0 + 4];
        unsigned int b10 = bw[ib_base + d0 + 8 * 512];
        unsigned int b11 = bw[ib_base + d0 + 8 * 512 + 4];
        MMA_BF16(c0, c1, c2, c3, a0, a1, a2, a3, b00, b01);
        MMA_BF16(c4, c5, c6, c7, a0, a1, a2, a3, b10, b11);
    }

    __half2* o1 = g_acth + ((size_t)k * BATCH + b0 + g) * 8;
    __half2* o2 = o1 + 8 * 8;
    o1[tig]     = __float22half2_rn(make_float2(c0, c1));
    o1[4 + tig] = __float22half2_rn(make_float2(c4, c5));
    o2[tig]     = __float22half2_rn(make_float2(c2, c3));
    o2[4 + tig] = __float22half2_rn(make_float2(c6, c7));
}

// ---------------------------------------------------------------------------
// Kernel B: symmetric pairwise, half2, 2 columns per iteration.
// Dual exp via h2exp (one MUFU for both c's); one packed-HADD2 shfl chain
// reduces BOTH column sums at once (halves the symmetry tax).
// ---------------------------------------------------------------------------
__global__ void __launch_bounds__(256) mbd_pairwise_kernel()
{
    const int k    = blockIdx.x;
    const int tid  = threadIdx.x;
    const int lane = tid & 31;
    const int w    = tid >> 5;
    const int bsub = w & 3;
    const int ch   = w >> 2;
    const int2 pr  = c_pairs[blockIdx.y];
    const int i_t  = pr.x, j_t = pr.y;
    const bool diag = (i_t == j_t);

    __shared__ uint4 sA[128 * 2];
    __shared__ uint4 sB[128 * 2];
    __shared__ float scol[8][64];
    __shared__ float srow[256];

    const uint4* actk = reinterpret_cast<const uint4*>(
        g_acth + (size_t)k * BATCH * 8);

    sA[tid] = actk[(size_t)i_t * 256 + tid];
    sB[tid] = actk[(size_t)j_t * 256 + tid];
    reinterpret_cast<float*>(scol)[tid]       = 0.f;
    reinterpret_cast<float*>(scol)[tid + 256] = 0.f;
    __syncthreads();

    const int bl = bsub * 32 + lane;
    __half2 a[8];
    {
        uint4 p0 = sA[bl * 2 + 0];
        uint4 p1 = sA[bl * 2 + 1];
        a[0] = *reinterpret_cast<__half2*>(&p0.x);
        a[1] = *reinterpret_cast<__half2*>(&p0.y);
        a[2] = *reinterpret_cast<__half2*>(&p0.z);
        a[3] = *reinterpret_cast<__half2*>(&p0.w);
        a[4] = *reinterpret_cast<__half2*>(&p1.x);
        a[5] = *reinterpret_cast<__half2*>(&p1.y);
        a[6] = *reinterpret_cast<__half2*>(&p1.z);
        a[7] = *reinterpret_cast<__half2*>(&p1.w);
    }

    float f = 0.f;
    const int c_beg = ch * 64;

#define HAD(x, y) __habs2(__hsub2(x, y))
#define H2(u) (*reinterpret_cast<const __half2*>(&(u)))

#pragma unroll 4
    for (int cc = 0; cc < 32; cc++) {
        const int c0 = c_beg + 2 * cc;
        uint4 p0 = sB[c0 * 2 + 0];
        uint4 p1 = sB[c0 * 2 + 1];
        uint4 q0 = sB[c0 * 2 + 2];
        uint4 q1 = sB[c0 * 2 + 3];

        // tree for column c0
        __half2 t0 = __hadd2(HAD(a[0], H2(p0.x)), HAD(a[1], H2(p0.y)));
        __half2 t1 = __hadd2(HAD(a[2], H2(p0.z)), HAD(a[3], H2(p0.w)));
        __half2 t2 = __hadd2(HAD(a[4], H2(p1.x)), HAD(a[5], H2(p1.y)));
        __half2 t3 = __hadd2(HAD(a[6], H2(p1.z)), HAD(a[7], H2(p1.w)));
        t0 = __hadd2(__hadd2(t0, t1), __hadd2(t2, t3));
        // tree for column c0+1
        __half2 u0 = __hadd2(HAD(a[0], H2(q0.x)), HAD(a[1], H2(q0.y)));
        __half2 u1 = __hadd2(HAD(a[2], H2(q0.z)), HAD(a[3], H2(q0.w)));
        __half2 u2 = __hadd2(HAD(a[4], H2(q1.x)), HAD(a[5], H2(q1.y)));
        __half2 u3 = __hadd2(HAD(a[6], H2(q1.z)), HAD(a[7], H2(q1.w)));
        u0 = __hadd2(__hadd2(u0, u1), __hadd2(u2, u3));

        // s2 = (dist_c0, dist_c1); dual exp in one shot
        __half2 s2 = __hadd2(__lows2half2(t0, u0), __highs2half2(t0, u0));
        __half2 e2 = h2exp(__hneg2(s2));
        float2 ef = __half22float2(e2);
        f += ef.x + ef.y;

        if (!diag) {
            // one packed shfl chain reduces BOTH column sums over 32 rows
            unsigned int ev = *reinterpret_cast<unsigned int*>(&e2);
#pragma unroll
            for (int m = 16; m >= 1; m >>= 1) {
                unsigned int ov = __shfl_xor_sync(0xffffffffu, ev, m);
                __half2 sum = __hadd2(*reinterpret_cast<__half2*>(&ev),
                                      *reinterpret_cast<__half2*>(&ov));
                ev = *reinterpret_cast<unsigned int*>(&sum);
            }
            if (lane == 0) {
                float2 cf = __half22float2(*reinterpret_cast<__half2*>(&ev));
                scol[w][2 * cc]     += cf.x;
                scol[w][2 * cc + 1] += cf.y;
            }
        }
    }
#undef HAD
#undef H2

    srow[tid] = f;
    __syncthreads();

    if (tid < 128) {
        float rt = srow[tid] + srow[tid + 128];
        g_pp[(((size_t)k * NTILE + i_t) * NTILE + j_t) * 128 + tid] = rt;
    }
    if (!diag && tid < 128) {
        const int c   = tid;
        const int cch = c >> 6;
        const int cl  = c & 63;
        float ct = scol[cch * 4 + 0][cl] + scol[cch * 4 + 1][cl]
                 + scol[cch * 4 + 2][cl] + scol[cch * 4 + 3][cl];
        g_pp[(((size_t)k * NTILE + j_t) * NTILE + i_t) * 128 + c] = ct;
    }
}

// ---------------------------------------------------------------------------
// Kernel C: assemble features from g_pp (x-copy now lives in the GEMM kernel).
// ---------------------------------------------------------------------------
__global__ void __launch_bounds__(256) mbd_assemble_kernel(float* __restrict__ out)
{
    const int gtid = blockIdx.x * 256 + threadIdx.x;   // 0..32767
    const int k = gtid >> 10;
    const int b = gtid & 1023;
    const int t = b >> 7;
    const int r = b & 127;
    const float* pp = g_pp + (((size_t)k * NTILE + t) * NTILE) * 128 + r;
    float s = 0.f;
#pragma unroll
    for (int j = 0; j < NTILE; j++)
        s += pp[j * 128];
    out[(size_t)b * OUT_COLS + INPUT_DIM + k] = s;
}

extern "C" void kernel_launch(void* const* d_in, const int* in_sizes, int n_in,
                              void* d_out, int out_size)
{
    (void)in_sizes; (void)n_in; (void)out_size;
    const float* x = (const float*)d_in[0];
    const float* W = (const float*)d_in[1];
    float* out = (float*)d_out;

    mbd_wconvert_kernel<<<NB_K, 256>>>(W);
    mbd_gemm_kernel<<<dim3(NB_K / 4, BATCH / 16), 128>>>(x, out);
    mbd_pairwise_kernel<<<dim3(NB_K, NPAIRS), 256>>>();
    mbd_assemble_kernel<<<NB_K * BATCH / 256, 256>>>(out);
}